// round 1
// baseline (speedup 1.0000x reference)
#include <cuda_runtime.h>
#include <cuda_bf16.h>

// ---------------- problem-size constants (fixed by this problem) -------------
#define MAXN   100000
#define MAXE   80000
#define NREL   8
#define INF    128
#define HID    32
#define NCOLS  (NREL*HID)      // 256
#define NGMAX  64
#define EPB    1024            // edges per block in scatter2

// ---------------- device scratch (static: no allocations allowed) ------------
__device__ __align__(128) float g_y1[(size_t)MAXN * NCOLS];   // x @ [W1_0..W1_7]
__device__ __align__(128) float g_h1[(size_t)MAXN * HID];     // layer-1 output
__device__ __align__(128) float g_rso[NREL * MAXN];           // rsqrt(max(deg_out,1))
__device__ __align__(128) float g_rsi[NREL * MAXN];           // rsqrt(max(deg_in,1))
__device__ __align__(128) int   g_dego[NREL * MAXN];
__device__ __align__(128) int   g_degi[NREL * MAXN];
__device__ __align__(128) int   g_cnt[NGMAX];
__device__ __align__(128) float g_V[NREL * HID * 2];          // W2_r @ Wc

// packed f32x2 fma (ptxas never auto-fuses; PTX-only path on sm_10x)
union F2U { float2 f; unsigned long long u; };
__device__ __forceinline__ float2 ffma2(float2 a, float2 b, float2 c) {
    F2U A, B, C, D; A.f = a; B.f = b; C.f = c;
    asm("fma.rn.f32x2 %0, %1, %2, %3;" : "=l"(D.u) : "l"(A.u), "l"(B.u), "l"(C.u));
    return D.f;
}

// ---------------- K1: zero scratch -------------------------------------------
__global__ void k_init(int n_nodes) {
    int i = blockIdx.x * blockDim.x + threadIdx.x;
    int a = NREL * n_nodes;
    if (i < a)                           g_dego[i] = 0;
    else if (i < 2 * a)                  g_degi[i - a] = 0;
    else if (i < 2 * a + HID * n_nodes)  g_h1[i - 2 * a] = 0.f;
    else if (i < 2 * a + HID * n_nodes + NGMAX) g_cnt[i - 2 * a - HID * n_nodes] = 0;
}

// ---------------- K2: degrees + per-graph node counts ------------------------
__global__ void k_deg(const int* __restrict__ src, const int* __restrict__ dst,
                      const int* __restrict__ gids, int n_nodes, int n_edges) {
    int i = blockIdx.x * blockDim.x + threadIdx.x;
    int te = NREL * n_edges;
    if (i < te) {
        int r = i / n_edges;
        atomicAdd(&g_dego[r * n_nodes + src[i]], 1);
        atomicAdd(&g_degi[r * n_nodes + dst[i]], 1);
    } else if (i < te + n_nodes) {
        atomicAdd(&g_cnt[gids[i - te]], 1);
    }
}

// ---------------- K3: rsqrt tables, V_r = W2_r @ Wc, output init --------------
__global__ void k_prep(const float* __restrict__ W2, const float* __restrict__ Wc,
                       const float* __restrict__ b2, const float* __restrict__ bc,
                       float* __restrict__ out, int n_nodes, int n_graphs) {
    int i = blockIdx.x * blockDim.x + threadIdx.x;
    int t1 = NREL * n_nodes;
    if (i < t1) {
        g_rso[i] = rsqrtf((float)max(g_dego[i], 1));
        g_rsi[i] = rsqrtf((float)max(g_degi[i], 1));
    } else if (i < t1 + NREL * HID * 2) {
        int v = i - t1;
        int r = v >> 6, f = (v >> 1) & 31, o = v & 1;
        float s = 0.f;
        #pragma unroll
        for (int j = 0; j < HID; j++) s += W2[r * (HID * HID) + f * HID + j] * Wc[j * 2 + o];
        g_V[v] = s;
    } else if (i < t1 + NREL * HID * 2 + 2 * n_graphs) {
        int u = i - t1 - NREL * HID * 2;
        int g = u >> 1, o = u & 1;
        float s = 0.f;
        for (int j = 0; j < HID; j++) {
            float bs = 0.f;
            #pragma unroll
            for (int r = 0; r < NREL; r++) bs += b2[r * HID + j];
            s += bs * Wc[j * 2 + o];
        }
        out[u] = bc[o] + (g_cnt[g] > 0 ? s : 0.f);   // empty graph -> pooled = 0
    }
}

// ---------------- K4: GEMM  y1[n, r*32+f] = x[n,:] @ W1[r,:,f] ----------------
// 128 nodes x 64 cols per block, 256 threads, packed f32x2 across node pairs.
__global__ __launch_bounds__(256) void k_gemm1(const float* __restrict__ x,
                                               const float* __restrict__ W1,
                                               int n_nodes) {
    __shared__ float  xs[32][130];    // [k][node], padded stride
    __shared__ float2 ws[32][64];     // [k][col], value duplicated in .x/.y
    int t = threadIdx.x;
    int node0 = blockIdx.x * 128;
    int c0 = blockIdx.y * 64;
    int p0 = (t >> 4) * 4;            // node-pair base (4 pairs = 8 nodes)
    int cl = (t & 15) * 4;            // col base (4 cols)

    float2 acc[4][4];
    #pragma unroll
    for (int i = 0; i < 4; i++)
        #pragma unroll
        for (int j = 0; j < 4; j++) acc[i][j] = make_float2(0.f, 0.f);

    for (int kc = 0; kc < 4; kc++) {
        int k0 = kc * 32;
        // stage x tile: 128 nodes x 32 k
        #pragma unroll
        for (int jj = 0; jj < 4; jj++) {
            int node = (t >> 3) + jj * 32;
            int kq = t & 7;
            int gn = node0 + node;
            float4 v = make_float4(0.f, 0.f, 0.f, 0.f);
            if (gn < n_nodes)
                v = *(const float4*)(x + (size_t)gn * INF + k0 + kq * 4);
            xs[kq * 4 + 0][node] = v.x;
            xs[kq * 4 + 1][node] = v.y;
            xs[kq * 4 + 2][node] = v.z;
            xs[kq * 4 + 3][node] = v.w;
        }
        // stage W tile: 32 k x 64 cols, duplicated for f32x2
        for (int idx = t; idx < 2048; idx += 256) {
            int k = idx >> 6, c = idx & 63;
            int col = c0 + c;
            float w = W1[(size_t)(col >> 5) * (INF * HID) + (size_t)(k0 + k) * HID + (col & 31)];
            ws[k][c] = make_float2(w, w);
        }
        __syncthreads();
        #pragma unroll 8
        for (int k = 0; k < 32; k++) {
            float2 xv[4], wv[4];
            #pragma unroll
            for (int i = 0; i < 4; i++) xv[i] = *(const float2*)&xs[k][2 * (p0 + i)];
            #pragma unroll
            for (int j = 0; j < 4; j++) wv[j] = ws[k][cl + j];
            #pragma unroll
            for (int i = 0; i < 4; i++)
                #pragma unroll
                for (int j = 0; j < 4; j++) acc[i][j] = ffma2(xv[i], wv[j], acc[i][j]);
        }
        __syncthreads();
    }
    #pragma unroll
    for (int i = 0; i < 4; i++) {
        int n0 = node0 + 2 * (p0 + i);
        if (n0 < n_nodes) {
            float4 v0 = make_float4(acc[i][0].x, acc[i][1].x, acc[i][2].x, acc[i][3].x);
            *(float4*)(g_y1 + (size_t)n0 * NCOLS + c0 + cl) = v0;
        }
        if (n0 + 1 < n_nodes) {
            float4 v1 = make_float4(acc[i][0].y, acc[i][1].y, acc[i][2].y, acc[i][3].y);
            *(float4*)(g_y1 + (size_t)(n0 + 1) * NCOLS + c0 + cl) = v1;
        }
    }
}

// ---------------- K5: layer-1 edge scatter (both deg scales folded) ----------
__global__ void k_scatter1(const int* __restrict__ src, const int* __restrict__ dst,
                           int n_nodes, int n_edges) {
    int i = blockIdx.x * blockDim.x + threadIdx.x;
    int tot = NREL * n_edges * 8;
    if (i >= tot) return;
    int e = i >> 3, q = i & 7;
    int r = e / n_edges;
    int s = src[e], d = dst[e];
    float sc = g_rso[r * n_nodes + s] * g_rsi[r * n_nodes + d];
    float4 v = *(const float4*)(g_y1 + (size_t)s * NCOLS + r * HID + q * 4);
    v.x *= sc; v.y *= sc; v.z *= sc; v.w *= sc;
    atomicAdd((float4*)(g_h1 + (size_t)d * HID + q * 4), v);
}

// ---------------- K6: bias + relu --------------------------------------------
__global__ void k_relu(const float* __restrict__ b1, int n_nodes) {
    __shared__ float bs[HID];
    if (threadIdx.x < HID) {
        float s = 0.f;
        #pragma unroll
        for (int r = 0; r < NREL; r++) s += b1[r * HID + threadIdx.x];
        bs[threadIdx.x] = s;
    }
    __syncthreads();
    int i = blockIdx.x * blockDim.x + threadIdx.x;
    if (i < n_nodes * HID) g_h1[i] = fmaxf(g_h1[i] + bs[i & 31], 0.f);
}

// -------- K7: fused layer-2 + mean-pool + classifier (edge -> out[64,2]) -----
__global__ __launch_bounds__(256) void k_scatter2(const int* __restrict__ src,
                                                  const int* __restrict__ dst,
                                                  const int* __restrict__ gids,
                                                  float* __restrict__ out,
                                                  int n_nodes, int n_edges) {
    __shared__ float zs[NGMAX * 2];
    __shared__ float Vs[NREL * HID * 2];
    __shared__ float inv_s[NGMAX];
    int t = threadIdx.x;
    if (t < NGMAX * 2) zs[t] = 0.f;
    for (int i = t; i < NREL * HID * 2; i += 256) Vs[i] = g_V[i];
    if (t < NGMAX) inv_s[t] = 1.f / (float)max(g_cnt[t], 1);
    __syncthreads();

    int te = NREL * n_edges;
    int e0 = blockIdx.x * EPB;
    #pragma unroll
    for (int it = 0; it < EPB / 256; it++) {
        int e = e0 + it * 256 + t;
        if (e < te) {
            int r = e / n_edges;
            int s = src[e], d = dst[e];
            int g = gids[d];
            float coeff = g_rso[r * n_nodes + s] * g_rsi[r * n_nodes + d] * inv_s[g];
            const float4* hp = (const float4*)(g_h1 + (size_t)s * HID);
            const float* vp = Vs + r * (HID * 2);
            float a0 = 0.f, a1 = 0.f;
            #pragma unroll
            for (int q = 0; q < 8; q++) {
                float4 hv = hp[q];
                a0 += hv.x * vp[q * 8 + 0] + hv.y * vp[q * 8 + 2] +
                      hv.z * vp[q * 8 + 4] + hv.w * vp[q * 8 + 6];
                a1 += hv.x * vp[q * 8 + 1] + hv.y * vp[q * 8 + 3] +
                      hv.z * vp[q * 8 + 5] + hv.w * vp[q * 8 + 7];
            }
            atomicAdd(&zs[g * 2 + 0], a0 * coeff);
            atomicAdd(&zs[g * 2 + 1], a1 * coeff);
        }
    }
    __syncthreads();
    if (t < NGMAX * 2) atomicAdd(&out[t], zs[t]);
}

// ---------------- launch ------------------------------------------------------
extern "C" void kernel_launch(void* const* d_in, const int* in_sizes, int n_in,
                              void* d_out, int out_size) {
    // inputs: x, src, dst, graph_ids, [num_graphs scalar], W1, b1, W2, b2, Wc, bc
    int off = (n_in >= 11) ? 1 : 0;
    const float* x   = (const float*)d_in[0];
    const int*   src = (const int*)d_in[1];
    const int*   dst = (const int*)d_in[2];
    const int*   gid = (const int*)d_in[3];
    const float* W1  = (const float*)d_in[4 + off];
    const float* b1  = (const float*)d_in[5 + off];
    const float* W2  = (const float*)d_in[6 + off];
    const float* b2  = (const float*)d_in[7 + off];
    const float* Wc  = (const float*)d_in[8 + off];
    const float* bc  = (const float*)d_in[9 + off];
    float* out = (float*)d_out;

    int n_nodes  = in_sizes[3];
    int n_edges  = in_sizes[1] / NREL;
    int n_graphs = out_size / 2;

    int tot0 = 2 * NREL * n_nodes + HID * n_nodes + NGMAX;
    k_init<<<(tot0 + 255) / 256, 256>>>(n_nodes);

    int tot1 = NREL * n_edges + n_nodes;
    k_deg<<<(tot1 + 255) / 256, 256>>>(src, dst, gid, n_nodes, n_edges);

    int tot2 = NREL * n_nodes + NREL * HID * 2 + 2 * n_graphs;
    k_prep<<<(tot2 + 255) / 256, 256>>>(W2, Wc, b2, bc, out, n_nodes, n_graphs);

    dim3 g4((n_nodes + 127) / 128, NCOLS / 64);
    k_gemm1<<<g4, 256>>>(x, W1, n_nodes);

    int tot5 = NREL * n_edges * 8;
    k_scatter1<<<(tot5 + 255) / 256, 256>>>(src, dst, n_nodes, n_edges);

    int tot6 = HID * n_nodes;
    k_relu<<<(tot6 + 255) / 256, 256>>>(b1, n_nodes);

    k_scatter2<<<(NREL * n_edges + EPB - 1) / EPB, 256>>>(src, dst, gid, out,
                                                          n_nodes, n_edges);
}

// round 3
// speedup vs baseline: 1.3649x; 1.3649x over previous
#include <cuda_runtime.h>
#include <cuda_bf16.h>

// ---------------- problem-size constants (fixed by this problem) -------------
#define MAXN   100000
#define MAXE   80000
#define NREL   8
#define INF    128
#define HID    32
#define NCOLS  (NREL*HID)      // 256
#define NGMAX  64
#define EPB    1024            // edges per block in scatter2

// ---------------- device scratch (static: no allocations allowed) ------------
__device__ __align__(128) float g_y1[(size_t)MAXN * NCOLS];   // x @ [W1_0..W1_7]
__device__ __align__(128) float g_h1[(size_t)MAXN * HID];     // layer-1 output
__device__ __align__(128) float g_rso[NREL * MAXN];           // rsqrt(max(deg_out,1))
__device__ __align__(128) float g_rsi[NREL * MAXN];           // rsqrt(max(deg_in,1))
__device__ __align__(128) int   g_dego[NREL * MAXN];
__device__ __align__(128) int   g_degi[NREL * MAXN];
__device__ __align__(128) int   g_cnt[NGMAX];
__device__ __align__(128) float g_V[NREL * HID * 2];          // W2_r @ Wc

// packed f32x2 fma (ptxas never auto-fuses; PTX-only path on sm_10x)
union F2U { float2 f; unsigned long long u; };
__device__ __forceinline__ float2 ffma2(float2 a, float2 b, float2 c) {
    F2U A, B, C, D; A.f = a; B.f = b; C.f = c;
    asm("fma.rn.f32x2 %0, %1, %2, %3;" : "=l"(D.u) : "l"(A.u), "l"(B.u), "l"(C.u));
    return D.f;
}

// ---------------- K1: zero scratch -------------------------------------------
__global__ void k_init(int n_nodes) {
    int i = blockIdx.x * blockDim.x + threadIdx.x;
    int a = NREL * n_nodes;
    if (i < a)                           g_dego[i] = 0;
    else if (i < 2 * a)                  g_degi[i - a] = 0;
    else if (i < 2 * a + HID * n_nodes)  g_h1[i - 2 * a] = 0.f;
    else if (i < 2 * a + HID * n_nodes + NGMAX) g_cnt[i - 2 * a - HID * n_nodes] = 0;
}

// ---------------- K2: degrees + per-graph node counts ------------------------
__global__ void k_deg(const int* __restrict__ src, const int* __restrict__ dst,
                      const int* __restrict__ gids, int n_nodes, int n_edges) {
    int i = blockIdx.x * blockDim.x + threadIdx.x;
    int te = NREL * n_edges;
    if (i < te) {
        int r = i / n_edges;
        atomicAdd(&g_dego[r * n_nodes + src[i]], 1);
        atomicAdd(&g_degi[r * n_nodes + dst[i]], 1);
    } else if (i < te + n_nodes) {
        atomicAdd(&g_cnt[gids[i - te]], 1);
    }
}

// ---------------- K3: rsqrt tables, V_r = W2_r @ Wc, output init --------------
__global__ void k_prep(const float* __restrict__ W2, const float* __restrict__ Wc,
                       const float* __restrict__ b2, const float* __restrict__ bc,
                       float* __restrict__ out, int n_nodes, int n_graphs) {
    int i = blockIdx.x * blockDim.x + threadIdx.x;
    int t1 = NREL * n_nodes;
    if (i < t1) {
        g_rso[i] = rsqrtf((float)max(g_dego[i], 1));
        g_rsi[i] = rsqrtf((float)max(g_degi[i], 1));
    } else if (i < t1 + NREL * HID * 2) {
        int v = i - t1;
        int r = v >> 6, f = (v >> 1) & 31, o = v & 1;
        float s = 0.f;
        #pragma unroll
        for (int j = 0; j < HID; j++) s += W2[r * (HID * HID) + f * HID + j] * Wc[j * 2 + o];
        g_V[v] = s;
    } else if (i < t1 + NREL * HID * 2 + 2 * n_graphs) {
        int u = i - t1 - NREL * HID * 2;
        int g = u >> 1, o = u & 1;
        float s = 0.f;
        for (int j = 0; j < HID; j++) {
            float bs = 0.f;
            #pragma unroll
            for (int r = 0; r < NREL; r++) bs += b2[r * HID + j];
            s += bs * Wc[j * 2 + o];
        }
        out[u] = bc[o] + (g_cnt[g] > 0 ? s : 0.f);   // empty graph -> pooled = 0
    }
}

// ---------------- K4: GEMM  y1[n, r*32+f] = x[n,:] @ W1[r,:,f] ----------------
// Block tile: 128 nodes x 128 cols. 256 threads, per-thread 8 nodes x 8 cols.
// x stored as node-pairs (float2) for packed fma.rn.f32x2; w stored UNduplicated.
// Row strides are multiples of 4 floats (16B) so all LDS.128/STS.128 stay aligned.
#define XS_LDF 132            // floats per xs row: 528B, 16B-aligned, bank skew 16
#define WS_LDF 132            // floats per ws row: 528B, 16B-aligned
__global__ __launch_bounds__(256, 2) void k_gemm1(const float* __restrict__ x,
                                                  const float* __restrict__ W1,
                                                  int n_nodes) {
    __shared__ float xs[32 * XS_LDF];   // [k][node]   128 nodes
    __shared__ float ws[32 * WS_LDF];   // [k][col]    128 cols
    int t = threadIdx.x;
    int node0 = blockIdx.x * 128;
    int c0 = blockIdx.y * 128;
    int tx = t & 15;                    // col group  (8 cols each)
    int ty = t >> 4;                    // node group (8 nodes = 4 pairs each)
    int ty4 = ty * 4;                   // first float2-pair index
    int tx8 = tx * 8;                   // first col

    float2 acc[4][8];
    #pragma unroll
    for (int i = 0; i < 4; i++)
        #pragma unroll
        for (int j = 0; j < 8; j++) acc[i][j] = make_float2(0.f, 0.f);

    for (int kc = 0; kc < 4; kc++) {
        int k0 = kc * 32;
        // ---- stage x tile: 128 nodes x 32 k (transpose to [k][node]) --------
        {
            int n = t >> 3;             // 0..31, +32 per pass
            int q = t & 7;              // k quarter (4 floats)
            #pragma unroll
            for (int jj = 0; jj < 4; jj++) {
                int node = n + jj * 32;
                int gn = node0 + node;
                float4 v = make_float4(0.f, 0.f, 0.f, 0.f);
                if (gn < n_nodes)
                    v = *(const float4*)(x + (size_t)gn * INF + k0 + q * 4);
                xs[(q * 4 + 0) * XS_LDF + node] = v.x;
                xs[(q * 4 + 1) * XS_LDF + node] = v.y;
                xs[(q * 4 + 2) * XS_LDF + node] = v.z;
                xs[(q * 4 + 3) * XS_LDF + node] = v.w;
            }
        }
        // ---- stage w tile: 32 k x 128 cols (4 relations), float4 loads ------
        {
            #pragma unroll
            for (int p = 0; p < 4; p++) {
                int idx = p * 256 + t;          // 0..1023
                int r = idx >> 8;               // relation within block (0..3)
                int k = (idx >> 3) & 31;
                int q = idx & 7;
                float4 w = *(const float4*)(W1 + (size_t)((c0 >> 5) + r) * (INF * HID)
                                               + (size_t)(k0 + k) * HID + q * 4);
                *(float4*)(ws + k * WS_LDF + r * 32 + q * 4) = w;
            }
        }
        __syncthreads();
        // ---- main loop -------------------------------------------------------
        #pragma unroll 4
        for (int k = 0; k < 32; k++) {
            float4 xa = *(const float4*)(xs + k * XS_LDF + ty4 * 2);
            float4 xb = *(const float4*)(xs + k * XS_LDF + ty4 * 2 + 4);
            float4 w0 = *(const float4*)(ws + k * WS_LDF + tx8);
            float4 w1 = *(const float4*)(ws + k * WS_LDF + tx8 + 4);
            float2 xv[4] = { make_float2(xa.x, xa.y), make_float2(xa.z, xa.w),
                             make_float2(xb.x, xb.y), make_float2(xb.z, xb.w) };
            float wsc[8] = { w0.x, w0.y, w0.z, w0.w, w1.x, w1.y, w1.z, w1.w };
            #pragma unroll
            for (int j = 0; j < 8; j++) {
                float2 wd = make_float2(wsc[j], wsc[j]);
                #pragma unroll
                for (int i = 0; i < 4; i++)
                    acc[i][j] = ffma2(xv[i], wd, acc[i][j]);
            }
        }
        __syncthreads();
    }
    // ---- epilogue: write y1 ---------------------------------------------------
    #pragma unroll
    for (int i = 0; i < 4; i++) {
        int pr = ty4 + i;               // pair index 0..63
        int n0 = node0 + pr * 2;
        if (n0 < n_nodes) {
            float4 v0 = make_float4(acc[i][0].x, acc[i][1].x, acc[i][2].x, acc[i][3].x);
            float4 v1 = make_float4(acc[i][4].x, acc[i][5].x, acc[i][6].x, acc[i][7].x);
            *(float4*)(g_y1 + (size_t)n0 * NCOLS + c0 + tx8)     = v0;
            *(float4*)(g_y1 + (size_t)n0 * NCOLS + c0 + tx8 + 4) = v1;
        }
        if (n0 + 1 < n_nodes) {
            float4 v0 = make_float4(acc[i][0].y, acc[i][1].y, acc[i][2].y, acc[i][3].y);
            float4 v1 = make_float4(acc[i][4].y, acc[i][5].y, acc[i][6].y, acc[i][7].y);
            *(float4*)(g_y1 + (size_t)(n0 + 1) * NCOLS + c0 + tx8)     = v0;
            *(float4*)(g_y1 + (size_t)(n0 + 1) * NCOLS + c0 + tx8 + 4) = v1;
        }
    }
}

// ---------------- K5: layer-1 edge scatter (both deg scales folded) ----------
__global__ void k_scatter1(const int* __restrict__ src, const int* __restrict__ dst,
                           int n_nodes, int n_edges) {
    int i = blockIdx.x * blockDim.x + threadIdx.x;
    int tot = NREL * n_edges * 8;
    if (i >= tot) return;
    int e = i >> 3, q = i & 7;
    int r = e / n_edges;
    int s = src[e], d = dst[e];
    float sc = g_rso[r * n_nodes + s] * g_rsi[r * n_nodes + d];
    float4 v = *(const float4*)(g_y1 + (size_t)s * NCOLS + r * HID + q * 4);
    v.x *= sc; v.y *= sc; v.z *= sc; v.w *= sc;
    atomicAdd((float4*)(g_h1 + (size_t)d * HID + q * 4), v);
}

// ---------------- K6: bias + relu --------------------------------------------
__global__ void k_relu(const float* __restrict__ b1, int n_nodes) {
    __shared__ float bs[HID];
    if (threadIdx.x < HID) {
        float s = 0.f;
        #pragma unroll
        for (int r = 0; r < NREL; r++) s += b1[r * HID + threadIdx.x];
        bs[threadIdx.x] = s;
    }
    __syncthreads();
    int i = blockIdx.x * blockDim.x + threadIdx.x;
    if (i < n_nodes * HID) g_h1[i] = fmaxf(g_h1[i] + bs[i & 31], 0.f);
}

// -------- K7: fused layer-2 + mean-pool + classifier (edge -> out[64,2]) -----
__global__ __launch_bounds__(256) void k_scatter2(const int* __restrict__ src,
                                                  const int* __restrict__ dst,
                                                  const int* __restrict__ gids,
                                                  float* __restrict__ out,
                                                  int n_nodes, int n_edges) {
    __shared__ float zs[NGMAX * 2];
    __shared__ float Vs[NREL * HID * 2];
    __shared__ float inv_s[NGMAX];
    int t = threadIdx.x;
    if (t < NGMAX * 2) zs[t] = 0.f;
    for (int i = t; i < NREL * HID * 2; i += 256) Vs[i] = g_V[i];
    if (t < NGMAX) inv_s[t] = 1.f / (float)max(g_cnt[t], 1);
    __syncthreads();

    int te = NREL * n_edges;
    int e0 = blockIdx.x * EPB;
    #pragma unroll
    for (int it = 0; it < EPB / 256; it++) {
        int e = e0 + it * 256 + t;
        if (e < te) {
            int r = e / n_edges;
            int s = src[e], d = dst[e];
            int g = gids[d];
            float coeff = g_rso[r * n_nodes + s] * g_rsi[r * n_nodes + d] * inv_s[g];
            const float4* hp = (const float4*)(g_h1 + (size_t)s * HID);
            const float* vp = Vs + r * (HID * 2);
            float a0 = 0.f, a1 = 0.f;
            #pragma unroll
            for (int q = 0; q < 8; q++) {
                float4 hv = hp[q];
                a0 += hv.x * vp[q * 8 + 0] + hv.y * vp[q * 8 + 2] +
                      hv.z * vp[q * 8 + 4] + hv.w * vp[q * 8 + 6];
                a1 += hv.x * vp[q * 8 + 1] + hv.y * vp[q * 8 + 3] +
                      hv.z * vp[q * 8 + 5] + hv.w * vp[q * 8 + 7];
            }
            atomicAdd(&zs[g * 2 + 0], a0 * coeff);
            atomicAdd(&zs[g * 2 + 1], a1 * coeff);
        }
    }
    __syncthreads();
    if (t < NGMAX * 2) atomicAdd(&out[t], zs[t]);
}

// ---------------- launch ------------------------------------------------------
extern "C" void kernel_launch(void* const* d_in, const int* in_sizes, int n_in,
                              void* d_out, int out_size) {
    // inputs: x, src, dst, graph_ids, [num_graphs scalar], W1, b1, W2, b2, Wc, bc
    int off = (n_in >= 11) ? 1 : 0;
    const float* x   = (const float*)d_in[0];
    const int*   src = (const int*)d_in[1];
    const int*   dst = (const int*)d_in[2];
    const int*   gid = (const int*)d_in[3];
    const float* W1  = (const float*)d_in[4 + off];
    const float* b1  = (const float*)d_in[5 + off];
    const float* W2  = (const float*)d_in[6 + off];
    const float* b2  = (const float*)d_in[7 + off];
    const float* Wc  = (const float*)d_in[8 + off];
    const float* bc  = (const float*)d_in[9 + off];
    float* out = (float*)d_out;

    int n_nodes  = in_sizes[3];
    int n_edges  = in_sizes[1] / NREL;
    int n_graphs = out_size / 2;

    int tot0 = 2 * NREL * n_nodes + HID * n_nodes + NGMAX;
    k_init<<<(tot0 + 255) / 256, 256>>>(n_nodes);

    int tot1 = NREL * n_edges + n_nodes;
    k_deg<<<(tot1 + 255) / 256, 256>>>(src, dst, gid, n_nodes, n_edges);

    int tot2 = NREL * n_nodes + NREL * HID * 2 + 2 * n_graphs;
    k_prep<<<(tot2 + 255) / 256, 256>>>(W2, Wc, b2, bc, out, n_nodes, n_graphs);

    dim3 g4((n_nodes + 127) / 128, NCOLS / 128);
    k_gemm1<<<g4, 256>>>(x, W1, n_nodes);

    int tot5 = NREL * n_edges * 8;
    k_scatter1<<<(tot5 + 255) / 256, 256>>>(src, dst, n_nodes, n_edges);

    int tot6 = HID * n_nodes;
    k_relu<<<(tot6 + 255) / 256, 256>>>(b1, n_nodes);

    k_scatter2<<<(NREL * n_edges + EPB - 1) / EPB, 256>>>(src, dst, gid, out,
                                                          n_nodes, n_edges);
}

// round 5
// speedup vs baseline: 1.7864x; 1.3088x over previous
#include <cuda_runtime.h>
#include <cuda_bf16.h>
#include <cstdint>

// ---------------- problem-size constants (fixed by this problem) -------------
#define MAXN   100000
#define NREL   8
#define INF    128
#define HID    32
#define NCOLS  (NREL*HID)      // 256
#define NGMAX  64
#define EPB    1024            // edges per block in scatter2

// ---------------- device scratch (static: no allocations allowed) ------------
__device__ __align__(128) float g_y1[(size_t)MAXN * NCOLS];   // x @ [W1_0..W1_7]
__device__ __align__(128) float g_h1[(size_t)MAXN * HID];     // layer-1 output
__device__ __align__(128) float g_rso[NREL * MAXN];           // rsqrt(max(deg_out,1))
__device__ __align__(128) float g_rsi[NREL * MAXN];           // rsqrt(max(deg_in,1))
__device__ __align__(128) int   g_dego[NREL * MAXN];
__device__ __align__(128) int   g_degi[NREL * MAXN];
__device__ __align__(128) int   g_cnt[NGMAX];
__device__ __align__(128) float g_V[NREL * HID * 2];          // W2_r @ Wc
// bf16 hi/lo weight image, [n][k] layout (k contiguous, 256B/row):
// [0,64K) = B_hi (256 n-rows x 128 k), [64K,128K) = B_lo
__device__ __align__(128) unsigned char g_wimg[131072];

// ---------------- K1: zero scratch -------------------------------------------
__global__ void k_init(int n_nodes) {
    int i = blockIdx.x * blockDim.x + threadIdx.x;
    int a = NREL * n_nodes;
    if (i < a)                           g_dego[i] = 0;
    else if (i < 2 * a)                  g_degi[i - a] = 0;
    else if (i < 2 * a + HID * n_nodes)  g_h1[i - 2 * a] = 0.f;
    else if (i < 2 * a + HID * n_nodes + NGMAX) g_cnt[i - 2 * a - HID * n_nodes] = 0;
}

// ---------------- K2: degrees + per-graph node counts ------------------------
__global__ void k_deg(const int* __restrict__ src, const int* __restrict__ dst,
                      const int* __restrict__ gids, int n_nodes, int n_edges) {
    int i = blockIdx.x * blockDim.x + threadIdx.x;
    int te = NREL * n_edges;
    if (i < te) {
        int r = i / n_edges;
        atomicAdd(&g_dego[r * n_nodes + src[i]], 1);
        atomicAdd(&g_degi[r * n_nodes + dst[i]], 1);
    } else if (i < te + n_nodes) {
        atomicAdd(&g_cnt[gids[i - te]], 1);
    }
}

// ---------------- K3: rsqrt tables, V_r = W2_r @ Wc, output init --------------
__global__ void k_prep(const float* __restrict__ W2, const float* __restrict__ Wc,
                       const float* __restrict__ b2, const float* __restrict__ bc,
                       float* __restrict__ out, int n_nodes, int n_graphs) {
    int i = blockIdx.x * blockDim.x + threadIdx.x;
    int t1 = NREL * n_nodes;
    if (i < t1) {
        g_rso[i] = rsqrtf((float)max(g_dego[i], 1));
        g_rsi[i] = rsqrtf((float)max(g_degi[i], 1));
    } else if (i < t1 + NREL * HID * 2) {
        int v = i - t1;
        int r = v >> 6, f = (v >> 1) & 31, o = v & 1;
        float s = 0.f;
        #pragma unroll
        for (int j = 0; j < HID; j++) s += W2[r * (HID * HID) + f * HID + j] * Wc[j * 2 + o];
        g_V[v] = s;
    } else if (i < t1 + NREL * HID * 2 + 2 * n_graphs) {
        int u = i - t1 - NREL * HID * 2;
        int g = u >> 1, o = u & 1;
        float s = 0.f;
        for (int j = 0; j < HID; j++) {
            float bs = 0.f;
            #pragma unroll
            for (int r = 0; r < NREL; r++) bs += b2[r * HID + j];
            s += bs * Wc[j * 2 + o];
        }
        out[u] = bc[o] + (g_cnt[g] > 0 ? s : 0.f);   // empty graph -> pooled = 0
    }
}

// ---------------- K3b: W1 -> bf16 hi/lo image, [n][k] layout ------------------
__global__ void k_wconv(const float* __restrict__ W1) {
    int i = blockIdx.x * blockDim.x + threadIdx.x;   // 0..16383
    if (i >= 256 * 64) return;
    int n = i >> 6, kp = (i & 63);                   // col n, k pair index
    int k = kp * 2;
    int r = n >> 5, f = n & 31;
    float w0 = W1[r * (INF * HID) + k * HID + f];
    float w1 = W1[r * (INF * HID) + (k + 1) * HID + f];
    __nv_bfloat16 h0 = __float2bfloat16(w0);
    __nv_bfloat16 h1 = __float2bfloat16(w1);
    __nv_bfloat16 l0 = __float2bfloat16(w0 - __bfloat162float(h0));
    __nv_bfloat16 l1 = __float2bfloat16(w1 - __bfloat162float(h1));
    uint32_t off = (uint32_t)n * 256u + (uint32_t)k * 2u;
    __nv_bfloat162 hv; hv.x = h0; hv.y = h1;
    __nv_bfloat162 lv; lv.x = l0; lv.y = l1;
    *(__nv_bfloat162*)(g_wimg + off) = hv;
    *(__nv_bfloat162*)(g_wimg + 65536 + off) = lv;
}

// ---------------- K4: HMMA GEMM  y1 = x @ [W1_0..W1_7] ------------------------
// CTA: 128 nodes x 128 cols x K=128. 8 warps (4M x 2N), warp tile 32x64.
// bf16 hi/lo split: 3 accumulating passes (hh, h*lo, lo*h).
// Smem rows padded to 272B so fragment LDS.32 (8 rows x 4 words) is conflict-free.
#define SROW  272                    // bytes per smem row (136 bf16)
#define SA_H  0
#define SA_L  (128 * SROW)           // 34816
#define SB_H  (2 * 128 * SROW)       // 69632
#define SB_L  (3 * 128 * SROW)       // 104448
#define SMEM_G (4 * 128 * SROW)      // 139264

__device__ __forceinline__ void mma16816(float* c, const uint32_t* a, const uint32_t* b) {
    asm volatile("mma.sync.aligned.m16n8k16.row.col.f32.bf16.bf16.f32 "
        "{%0,%1,%2,%3}, {%4,%5,%6,%7}, {%8,%9}, {%0,%1,%2,%3};"
        : "+f"(c[0]), "+f"(c[1]), "+f"(c[2]), "+f"(c[3])
        : "r"(a[0]), "r"(a[1]), "r"(a[2]), "r"(a[3]), "r"(b[0]), "r"(b[1]));
}

__global__ __launch_bounds__(256, 1) void k_gemm_mma(const float* __restrict__ x,
                                                     int n_nodes) {
    extern __shared__ unsigned char smem[];
    int t = threadIdx.x, wid = t >> 5, lid = t & 31;
    int gid = lid >> 2, tid4 = lid & 3;
    int node0 = blockIdx.x * 128;
    int cbase = blockIdx.y * 128;

    // ---- stage A (x tile) as bf16 hi/lo ---------------------------------------
    #pragma unroll
    for (int p = 0; p < 16; p++) {
        int idx = p * 256 + t;               // 0..4095
        int m = idx >> 5, k = (idx & 31) * 4;
        int gn = node0 + m;
        float4 v = make_float4(0.f, 0.f, 0.f, 0.f);
        if (gn < n_nodes) v = *(const float4*)(x + (size_t)gn * INF + k);
        __nv_bfloat16 h0 = __float2bfloat16(v.x), h1 = __float2bfloat16(v.y);
        __nv_bfloat16 h2 = __float2bfloat16(v.z), h3 = __float2bfloat16(v.w);
        __nv_bfloat16 l0 = __float2bfloat16(v.x - __bfloat162float(h0));
        __nv_bfloat16 l1 = __float2bfloat16(v.y - __bfloat162float(h1));
        __nv_bfloat16 l2 = __float2bfloat16(v.z - __bfloat162float(h2));
        __nv_bfloat16 l3 = __float2bfloat16(v.w - __bfloat162float(h3));
        __nv_bfloat162 a, b;
        a.x = h0; a.y = h1; b.x = h2; b.y = h3;
        uint2 hp; hp.x = *(uint32_t*)&a; hp.y = *(uint32_t*)&b;
        a.x = l0; a.y = l1; b.x = l2; b.y = l3;
        uint2 lp; lp.x = *(uint32_t*)&a; lp.y = *(uint32_t*)&b;
        *(uint2*)(smem + SA_H + m * SROW + k * 2) = hp;
        *(uint2*)(smem + SA_L + m * SROW + k * 2) = lp;
    }
    // ---- stage B (weight image half, already bf16 hi/lo) ----------------------
    {
        const uint4* bh = (const uint4*)(g_wimg + (size_t)blockIdx.y * 32768);
        const uint4* bl = (const uint4*)(g_wimg + 65536 + (size_t)blockIdx.y * 32768);
        #pragma unroll
        for (int p = 0; p < 8; p++) {
            int idx = p * 256 + t;           // 0..2047
            int r = idx >> 4, c = idx & 15;
            *(uint4*)(smem + SB_H + r * SROW + c * 16) = bh[idx];
            *(uint4*)(smem + SB_L + r * SROW + c * 16) = bl[idx];
        }
    }
    __syncthreads();

    int mrow0 = (wid & 3) * 32;
    int ncol0 = (wid >> 2) * 64;
    float acc[2][8][4];
    #pragma unroll
    for (int mi = 0; mi < 2; mi++)
        #pragma unroll
        for (int ni = 0; ni < 8; ni++)
            #pragma unroll
            for (int q = 0; q < 4; q++) acc[mi][ni][q] = 0.f;

    #pragma unroll
    for (int pass = 0; pass < 3; pass++) {
        int ab = (pass == 2) ? SA_L : SA_H;
        int bb = (pass == 1) ? SB_L : SB_H;
        const unsigned char* ap = smem + ab + (mrow0 + gid) * SROW + tid4 * 4;
        const unsigned char* bp = smem + bb + (ncol0 + gid) * SROW + tid4 * 4;
        #pragma unroll
        for (int ks = 0; ks < 8; ks++) {
            int kb = ks * 32;
            uint32_t afr[2][4];
            #pragma unroll
            for (int mi = 0; mi < 2; mi++) {
                const unsigned char* a0 = ap + mi * 16 * SROW + kb;
                afr[mi][0] = *(const uint32_t*)(a0);
                afr[mi][1] = *(const uint32_t*)(a0 + 8 * SROW);
                afr[mi][2] = *(const uint32_t*)(a0 + 16);
                afr[mi][3] = *(const uint32_t*)(a0 + 8 * SROW + 16);
            }
            #pragma unroll
            for (int ni = 0; ni < 8; ni++) {
                const unsigned char* b0 = bp + ni * 8 * SROW + kb;
                uint32_t bfr[2];
                bfr[0] = *(const uint32_t*)(b0);
                bfr[1] = *(const uint32_t*)(b0 + 16);
                mma16816(acc[0][ni], afr[0], bfr);
                mma16816(acc[1][ni], afr[1], bfr);
            }
        }
    }

    // ---- epilogue: write y1 ----------------------------------------------------
    #pragma unroll
    for (int mi = 0; mi < 2; mi++) {
        int r0 = node0 + mrow0 + mi * 16 + gid;
        #pragma unroll
        for (int ni = 0; ni < 8; ni++) {
            int col = cbase + ncol0 + ni * 8 + tid4 * 2;
            if (r0 < n_nodes)
                *(float2*)(g_y1 + (size_t)r0 * NCOLS + col) =
                    make_float2(acc[mi][ni][0], acc[mi][ni][1]);
            if (r0 + 8 < n_nodes)
                *(float2*)(g_y1 + (size_t)(r0 + 8) * NCOLS + col) =
                    make_float2(acc[mi][ni][2], acc[mi][ni][3]);
        }
    }
}

// ---------------- K5: layer-1 edge scatter (both deg scales folded) ----------
__global__ void k_scatter1(const int* __restrict__ src, const int* __restrict__ dst,
                           int n_nodes, int n_edges) {
    int i = blockIdx.x * blockDim.x + threadIdx.x;
    int tot = NREL * n_edges * 8;
    if (i >= tot) return;
    int e = i >> 3, q = i & 7;
    int r = e / n_edges;
    int s = src[e], d = dst[e];
    float sc = g_rso[r * n_nodes + s] * g_rsi[r * n_nodes + d];
    float4 v = *(const float4*)(g_y1 + (size_t)s * NCOLS + r * HID + q * 4);
    v.x *= sc; v.y *= sc; v.z *= sc; v.w *= sc;
    atomicAdd((float4*)(g_h1 + (size_t)d * HID + q * 4), v);
}

// ---------------- K6: bias + relu --------------------------------------------
__global__ void k_relu(const float* __restrict__ b1, int n_nodes) {
    __shared__ float bs[HID];
    if (threadIdx.x < HID) {
        float s = 0.f;
        #pragma unroll
        for (int r = 0; r < NREL; r++) s += b1[r * HID + threadIdx.x];
        bs[threadIdx.x] = s;
    }
    __syncthreads();
    int i = blockIdx.x * blockDim.x + threadIdx.x;
    if (i < n_nodes * HID) g_h1[i] = fmaxf(g_h1[i] + bs[i & 31], 0.f);
}

// -------- K7: fused layer-2 + mean-pool + classifier (edge -> out[64,2]) -----
__global__ __launch_bounds__(256) void k_scatter2(const int* __restrict__ src,
                                                  const int* __restrict__ dst,
                                                  const int* __restrict__ gids,
                                                  float* __restrict__ out,
                                                  int n_nodes, int n_edges) {
    __shared__ float zs[NGMAX * 2];
    __shared__ float Vs[NREL * HID * 2];
    __shared__ float inv_s[NGMAX];
    int t = threadIdx.x;
    if (t < NGMAX * 2) zs[t] = 0.f;
    for (int i = t; i < NREL * HID * 2; i += 256) Vs[i] = g_V[i];
    if (t < NGMAX) inv_s[t] = 1.f / (float)max(g_cnt[t], 1);
    __syncthreads();

    int te = NREL * n_edges;
    int e0 = blockIdx.x * EPB;
    #pragma unroll
    for (int it = 0; it < EPB / 256; it++) {
        int e = e0 + it * 256 + t;
        if (e < te) {
            int r = e / n_edges;
            int s = src[e], d = dst[e];
            int g = gids[d];
            float coeff = g_rso[r * n_nodes + s] * g_rsi[r * n_nodes + d] * inv_s[g];
            const float4* hp = (const float4*)(g_h1 + (size_t)s * HID);
            const float* vp = Vs + r * (HID * 2);
            float a0 = 0.f, a1 = 0.f;
            #pragma unroll
            for (int q = 0; q < 8; q++) {
                float4 hv = hp[q];
                a0 += hv.x * vp[q * 8 + 0] + hv.y * vp[q * 8 + 2] +
                      hv.z * vp[q * 8 + 4] + hv.w * vp[q * 8 + 6];
                a1 += hv.x * vp[q * 8 + 1] + hv.y * vp[q * 8 + 3] +
                      hv.z * vp[q * 8 + 5] + hv.w * vp[q * 8 + 7];
            }
            atomicAdd(&zs[g * 2 + 0], a0 * coeff);
            atomicAdd(&zs[g * 2 + 1], a1 * coeff);
        }
    }
    __syncthreads();
    if (t < NGMAX * 2) atomicAdd(&out[t], zs[t]);
}

// ---------------- launch ------------------------------------------------------
extern "C" void kernel_launch(void* const* d_in, const int* in_sizes, int n_in,
                              void* d_out, int out_size) {
    int off = (n_in >= 11) ? 1 : 0;
    const float* x   = (const float*)d_in[0];
    const int*   src = (const int*)d_in[1];
    const int*   dst = (const int*)d_in[2];
    const int*   gid = (const int*)d_in[3];
    const float* W1  = (const float*)d_in[4 + off];
    const float* b1  = (const float*)d_in[5 + off];
    const float* W2  = (const float*)d_in[6 + off];
    const float* b2  = (const float*)d_in[7 + off];
    const float* Wc  = (const float*)d_in[8 + off];
    const float* bc  = (const float*)d_in[9 + off];
    float* out = (float*)d_out;

    int n_nodes  = in_sizes[3];
    int n_edges  = in_sizes[1] / NREL;
    int n_graphs = out_size / 2;

    cudaFuncSetAttribute(k_gemm_mma, cudaFuncAttributeMaxDynamicSharedMemorySize,
                         SMEM_G);

    int tot0 = 2 * NREL * n_nodes + HID * n_nodes + NGMAX;
    k_init<<<(tot0 + 255) / 256, 256>>>(n_nodes);

    int tot1 = NREL * n_edges + n_nodes;
    k_deg<<<(tot1 + 255) / 256, 256>>>(src, dst, gid, n_nodes, n_edges);

    int tot2 = NREL * n_nodes + NREL * HID * 2 + 2 * n_graphs;
    k_prep<<<(tot2 + 255) / 256, 256>>>(W2, Wc, b2, bc, out, n_nodes, n_graphs);

    k_wconv<<<64, 256>>>(W1);

    dim3 g4((n_nodes + 127) / 128, 2);
    k_gemm_mma<<<g4, 256, SMEM_G>>>(x, n_nodes);

    int tot5 = NREL * n_edges * 8;
    k_scatter1<<<(tot5 + 255) / 256, 256>>>(src, dst, n_nodes, n_edges);

    int tot6 = HID * n_nodes;
    k_relu<<<(tot6 + 255) / 256, 256>>>(b1, n_nodes);

    k_scatter2<<<(NREL * n_edges + EPB - 1) / EPB, 256>>>(src, dst, gid, out,
                                                          n_nodes, n_edges);
}